// round 12
// baseline (speedup 1.0000x reference)
#include <cuda_runtime.h>
#include <cuda_fp16.h>
#include <cstdint>

// ---------------------------------------------------------------------------
// Problem constants
// ---------------------------------------------------------------------------
#define N_SEL 256
#define PTS   2048
#define D_IN  256
#define D_OUT 256
#define TILES 8

// 32 MB fp16 scratch: gathered+transposed weights, layout [c][n][k]
static __device__ __half g_wt[(size_t)N_SEL * D_OUT * D_IN];

// ---------------------------------------------------------------------------
// Helpers (generic PTX only — compute_103 target has no tcgen05/TMA-a features)
// ---------------------------------------------------------------------------
#define SWZ128(o) ((o) ^ (((o) >> 3) & 0x70))

static __device__ __forceinline__ uint32_t smem_u32(const void* p) {
    uint32_t a;
    asm("{ .reg .u64 t; cvta.to.shared.u64 t, %1; cvt.u32.u64 %0, t; }"
        : "=r"(a) : "l"(p));
    return a;
}

static __device__ __forceinline__ void ldmx4(uint32_t* r, uint32_t addr) {
    asm volatile("ldmatrix.sync.aligned.m8n8.x4.shared.b16 {%0,%1,%2,%3}, [%4];"
                 : "=r"(r[0]), "=r"(r[1]), "=r"(r[2]), "=r"(r[3]) : "r"(addr));
}

static __device__ __forceinline__ void mma16816(float* c, const uint32_t* a,
                                                const uint32_t* b) {
    asm volatile(
        "mma.sync.aligned.m16n8k16.row.col.f32.f16.f16.f32 "
        "{%0,%1,%2,%3}, {%4,%5,%6,%7}, {%8,%9}, {%0,%1,%2,%3};"
        : "+f"(c[0]), "+f"(c[1]), "+f"(c[2]), "+f"(c[3])
        : "r"(a[0]), "r"(a[1]), "r"(a[2]), "r"(a[3]), "r"(b[0]), "r"(b[1]));
}

#define CP_ASYNC16(smem_addr, gptr) \
    asm volatile("cp.async.cg.shared.global [%0], [%1], 16;" \
                 :: "r"(smem_addr), "l"(gptr) : "memory")
#define CP_COMMIT() asm volatile("cp.async.commit_group;" ::: "memory")
#define CP_WAIT0()  asm volatile("cp.async.wait_group 0;" ::: "memory")

// ---------------------------------------------------------------------------
// indices may be int32 or int64 (JAX x64 flag unknown). For int64, the odd
// 32-bit words of non-negative values < 256 are all zero; for int32 random
// values in [0,256) they are almost surely not. P(misdetect) ~= 256^-16.
// ---------------------------------------------------------------------------
static __device__ __forceinline__ int sel_index(const void* idx_raw, int c) {
    const int* pi = (const int*)idx_raw;
    int odd_or = 0;
#pragma unroll
    for (int j = 0; j < 16; ++j) odd_or |= pi[2 * j + 1];
    return (odd_or == 0) ? pi[2 * c] : pi[c];
}

// ---------------------------------------------------------------------------
// Pre-pass: g_wt[c][n][k] = (half) weight[idx[c]][t][k][n]
// Grid: 256 channels x 8 k-tiles x 8 n-tiles, 256 threads, 32x32 smem tiles.
// ---------------------------------------------------------------------------
__global__ void __launch_bounds__(256) wt_gather_transpose_kernel(
    const float* __restrict__ weight,
    const void* __restrict__ idx_raw,
    const int* __restrict__ t_ptr)
{
    __shared__ float tile[32][33];
    int bid = blockIdx.x;
    int c = bid >> 6;
    int rem = bid & 63;
    int kt = rem >> 3, nt = rem & 7;

    int t = t_ptr ? *t_ptr : 3;   // low 32-bit word valid for int32 and int64
    int ch = sel_index(idx_raw, c);

    const float* src = weight + (((size_t)ch * TILES + t) << 16);
    int tx = threadIdx.x & 31, ty = threadIdx.x >> 5;

#pragma unroll
    for (int i = 0; i < 4; ++i)
        tile[ty + i * 8][tx] = src[(size_t)(kt * 32 + ty + i * 8) * 256 + nt * 32 + tx];
    __syncthreads();

    __half* dst = g_wt + (((size_t)c * 256 + nt * 32) << 8) + kt * 32;
#pragma unroll
    for (int i = 0; i < 4; ++i)
        dst[(size_t)(ty + i * 8) * 256 + tx] = __float2half_rn(tile[tx][ty + i * 8]);
}

// ---------------------------------------------------------------------------
// Main kernel: one CTA per (channel, 64-pt tile, 128-out tile).
// 256 threads / 8 warps (2m x 4n), warp tile 32x32, mma.sync.m16n8k16.
// 3 CTAs/SM (<=84 regs, ~49 KB smem each): 24 warps/SM in three independent
// barrier domains — attacks the latency-exposure limit that R7-R11 hit
// (no pipe above 55%, issue 16%). x tiles are read by the 2 n-sibling CTAs;
// grid is n-fastest so the second read hits L2.
// K=256 in 4 chunks of 64, double-buffered A (8 KB fp32->fp16 staged via
// regs) and B (16 KB via cp.async from the fp16 weight scratch).
// ---------------------------------------------------------------------------
#define OFF_A0   0u
#define OFF_A1   8192u
#define OFF_B0   16384u
#define OFF_B1   32768u
#define OFF_BIAS 49152u      // 128 floats
#define SMEM_DYN (49664u + 1024u)   // + pad for 1024B alignment

__global__ void __launch_bounds__(256, 3)
adaptive_linear_main_kernel(
    const float* __restrict__ x,
    const float* __restrict__ bias,
    const void* __restrict__ idx_raw,
    const int* __restrict__ t_ptr,
    float* __restrict__ out)
{
    extern __shared__ char dyn_smem[];
    uint32_t raw = smem_u32(dyn_smem);
    uint32_t sb = (raw + 1023u) & ~1023u;      // 1024B-aligned base for SW128
    char* sp = dyn_smem + (sb - raw);

    int tid = threadIdx.x;
    int wid = tid >> 5, lid = tid & 31;
    int c  = blockIdx.z;
    int m0 = blockIdx.y * 64;
    int n0 = blockIdx.x * 128;

    int t = t_ptr ? *t_ptr : 3;
    int ch = sel_index(idx_raw, c);
    if (tid < 128)
        ((float*)(sp + OFF_BIAS))[tid] =
            bias[(((size_t)ch * TILES + t) << 8) + n0 + tid];

    const float*  xA = x + (((size_t)c * PTS + m0) << 8);
    const __half* wB = g_wt + ((size_t)c << 16) + ((size_t)n0 << 8);

    // per-thread load mapping
    int arow = tid >> 4;            // A: 64 rows, 16 threads/row, 4 row-groups
    int aq   = tid & 15;            // float4 index within 64-float chunk row
    int bn   = tid >> 1;            // B: 128 rows, 2 threads/row
    int bj0  = (tid & 1) * 4;       // 4 x 16B segments each

    float4 pa[4];                   // A staging registers (16 floats)

    // ---- A chunk LDG into regs (64 rows x 64 k, coalesced) ----------------
    auto ldgA = [&](int kc) {
        const float* base = xA + kc * 64 + aq * 4;
#pragma unroll
        for (int i = 0; i < 4; ++i)
            pa[i] = *(const float4*)(base + ((size_t)(arow + i * 16) << 8));
    };
    // ---- A regs -> fp16 swizzled STS into buffer abase --------------------
    auto stsA = [&](uint32_t abase) {
#pragma unroll
        for (int i = 0; i < 4; ++i) {
            __half2 h0 = __floats2half2_rn(pa[i].x, pa[i].y);
            __half2 h1 = __floats2half2_rn(pa[i].z, pa[i].w);
            uint2 u;
            u.x = *reinterpret_cast<uint32_t*>(&h0);
            u.y = *reinterpret_cast<uint32_t*>(&h1);
            uint32_t o = (uint32_t)((arow + i * 16) * 128 + aq * 8);
            *reinterpret_cast<uint2*>(sp + abase + SWZ128(o)) = u;
        }
    };
    // ---- B chunk cp.async (128 n-rows x 64 k) -----------------------------
    auto cpB = [&](int kc, uint32_t bbase) {
#pragma unroll
        for (int i = 0; i < 4; ++i) {
            int j = bj0 + i;
            uint32_t o = (uint32_t)(bn * 128 + j * 16);
            const __half* g = wB + ((size_t)bn << 8) + kc * 64 + j * 8;
            CP_ASYNC16(sb + bbase + SWZ128(o), g);
        }
    };

    // warp tile origin (8 warps: 2 m x 4 n)
    int mrow0 = (wid & 1) * 32;
    int ncol0 = (wid >> 1) * 32;
    // ldmatrix per-lane bases
    uint32_t aRow  = (uint32_t)(mrow0 + (lid & 15));
    uint32_t aKoff = (uint32_t)((lid >> 4) * 16);          // bytes
    uint32_t bRow  = (uint32_t)(ncol0 + ((lid >> 4) << 3) + (lid & 7));
    uint32_t bKoff = (uint32_t)(((lid >> 3) & 1) * 16);    // bytes

    float acc[2][4][4];
#pragma unroll
    for (int mt = 0; mt < 2; ++mt)
#pragma unroll
        for (int nt = 0; nt < 4; ++nt)
#pragma unroll
            for (int r = 0; r < 4; ++r) acc[mt][nt][r] = 0.f;

    // ---- one 16-wide k-step: 4 LDSM + 8 MMA, interleaved ------------------
    auto compute_ks = [&](uint32_t ab, uint32_t bb, int ks) {
        uint32_t a[2][4];
        uint32_t b[2][4];
#pragma unroll
        for (int mt = 0; mt < 2; ++mt) {
            uint32_t o = (aRow + mt * 16) * 128 + ks * 32 + aKoff;
            ldmx4(a[mt], ab + SWZ128(o));
        }
        {
            uint32_t o = (bRow + 0) * 128 + ks * 32 + bKoff;
            ldmx4(b[0], bb + SWZ128(o));
        }
#pragma unroll
        for (int mt = 0; mt < 2; ++mt)
#pragma unroll
            for (int nt = 0; nt < 2; ++nt)
                mma16816(acc[mt][nt], a[mt], &b[0][nt * 2]);
        {
            uint32_t o = (bRow + 16) * 128 + ks * 32 + bKoff;
            ldmx4(b[1], bb + SWZ128(o));
        }
#pragma unroll
        for (int mt = 0; mt < 2; ++mt)
#pragma unroll
            for (int nt = 2; nt < 4; ++nt)
                mma16816(acc[mt][nt], a[mt], &b[1][(nt - 2) * 2]);
    };

    // ---- prologue: chunk 0 -------------------------------------------------
    cpB(0, OFF_B0);
    CP_COMMIT();
    ldgA(0);
    stsA(OFF_A0);
    CP_WAIT0();
    __syncthreads();

    // ---- main loop: 4 chunks, double-buffered -----------------------------
    for (int kc = 0; kc < 4; ++kc) {
        uint32_t ab  = sb + ((kc & 1) ? OFF_A1 : OFF_A0);
        uint32_t bb  = sb + ((kc & 1) ? OFF_B1 : OFF_B0);
        uint32_t abN = (kc & 1) ? OFF_A0 : OFF_A1;
        uint32_t bbN = (kc & 1) ? OFF_B0 : OFF_B1;

        if (kc < 3) {
            cpB(kc + 1, bbN);
            CP_COMMIT();
            ldgA(kc + 1);           // DRAM/L2 load issued 2 compute blocks early
        }

        compute_ks(ab, bb, 0);
        compute_ks(ab, bb, 1);
        if (kc < 3) stsA(abN);
        compute_ks(ab, bb, 2);
        compute_ks(ab, bb, 3);

        if (kc < 3) {
            CP_WAIT0();
            __syncthreads();
        }
    }

    // ---- epilogue: accums + bias -> GMEM ----------------------------------
    {
        const float* bsm = (const float*)(sp + OFF_BIAS);
        int r0 = lid >> 2;
        int c0 = 2 * (lid & 3);
#pragma unroll
        for (int mt = 0; mt < 2; ++mt) {
            size_t rowg = (size_t)c * PTS + m0 + mrow0 + mt * 16 + r0;
#pragma unroll
            for (int nt = 0; nt < 4; ++nt) {
                int col = ncol0 + nt * 8 + c0;
                float b0 = bsm[col], b1 = bsm[col + 1];
                float2 v0 = make_float2(acc[mt][nt][0] + b0, acc[mt][nt][1] + b1);
                float2 v1 = make_float2(acc[mt][nt][2] + b0, acc[mt][nt][3] + b1);
                *reinterpret_cast<float2*>(out + (rowg << 8) + n0 + col) = v0;
                *reinterpret_cast<float2*>(out + ((rowg + 8) << 8) + n0 + col) = v1;
            }
        }
    }
}

// ---------------------------------------------------------------------------
// kernel_launch: pre-pass (gather/transpose/convert weights) then main GEMM.
// Inputs (metadata order): x, weight, bias, indices, t
// ---------------------------------------------------------------------------
extern "C" void kernel_launch(void* const* d_in, const int* in_sizes, int n_in,
                              void* d_out, int out_size)
{
    const float* x       = (const float*)d_in[0];
    const float* weight  = (const float*)d_in[1];
    const float* bias    = (const float*)d_in[2];
    const void*  indices = d_in[3];
    const int*   t_ptr   = (n_in >= 5) ? (const int*)d_in[4] : nullptr;
    float* out = (float*)d_out;

    cudaFuncSetAttribute(adaptive_linear_main_kernel,
                         cudaFuncAttributeMaxDynamicSharedMemorySize, SMEM_DYN);

    wt_gather_transpose_kernel<<<N_SEL * 64, 256>>>(weight, indices, t_ptr);
    // n-tile fastest so the 2 n-siblings sharing an x tile are co-resident
    adaptive_linear_main_kernel<<<dim3(2, 32, N_SEL), 256, SMEM_DYN>>>(
        x, bias, indices, t_ptr, out);
}

// round 13
// speedup vs baseline: 1.0708x; 1.0708x over previous
#include <cuda_runtime.h>
#include <cuda_fp16.h>
#include <cstdint>

// ---------------------------------------------------------------------------
// Problem constants
// ---------------------------------------------------------------------------
#define N_SEL 256
#define PTS   2048
#define D_IN  256
#define D_OUT 256
#define TILES 8

// 32 MB fp16 scratch: gathered+transposed weights, layout [c][n][k]
static __device__ __half g_wt[(size_t)N_SEL * D_OUT * D_IN];

// ---------------------------------------------------------------------------
// Helpers (generic PTX only — compute_103 target has no tcgen05/TMA-a features)
// ---------------------------------------------------------------------------
#define SWZ128(o) ((o) ^ (((o) >> 3) & 0x70))

static __device__ __forceinline__ uint32_t smem_u32(const void* p) {
    uint32_t a;
    asm("{ .reg .u64 t; cvta.to.shared.u64 t, %1; cvt.u32.u64 %0, t; }"
        : "=r"(a) : "l"(p));
    return a;
}

static __device__ __forceinline__ void ldmx4(uint32_t* r, uint32_t addr) {
    asm volatile("ldmatrix.sync.aligned.m8n8.x4.shared.b16 {%0,%1,%2,%3}, [%4];"
                 : "=r"(r[0]), "=r"(r[1]), "=r"(r[2]), "=r"(r[3]) : "r"(addr));
}

static __device__ __forceinline__ void mma16816(float* c, const uint32_t* a,
                                                const uint32_t* b) {
    asm volatile(
        "mma.sync.aligned.m16n8k16.row.col.f32.f16.f16.f32 "
        "{%0,%1,%2,%3}, {%4,%5,%6,%7}, {%8,%9}, {%0,%1,%2,%3};"
        : "+f"(c[0]), "+f"(c[1]), "+f"(c[2]), "+f"(c[3])
        : "r"(a[0]), "r"(a[1]), "r"(a[2]), "r"(a[3]), "r"(b[0]), "r"(b[1]));
}

#define CP_ASYNC16(smem_addr, gptr) \
    asm volatile("cp.async.cg.shared.global [%0], [%1], 16;" \
                 :: "r"(smem_addr), "l"(gptr) : "memory")
#define CP_COMMIT() asm volatile("cp.async.commit_group;" ::: "memory")
#define CP_WAIT0()  asm volatile("cp.async.wait_group 0;" ::: "memory")

// ---------------------------------------------------------------------------
// indices may be int32 or int64 (JAX x64 flag unknown). For int64, the odd
// 32-bit words of non-negative values < 256 are all zero; for int32 random
// values in [0,256) they are almost surely not. P(misdetect) ~= 256^-16.
// ---------------------------------------------------------------------------
static __device__ __forceinline__ int sel_index(const void* idx_raw, int c) {
    const int* pi = (const int*)idx_raw;
    int odd_or = 0;
#pragma unroll
    for (int j = 0; j < 16; ++j) odd_or |= pi[2 * j + 1];
    return (odd_or == 0) ? pi[2 * c] : pi[c];
}

// ---------------------------------------------------------------------------
// Pre-pass: g_wt[c][n][k] = (half) weight[idx[c]][t][k][n]
// Grid: 256 channels x 8 k-tiles x 8 n-tiles, 256 threads, 32x32 smem tiles.
// ---------------------------------------------------------------------------
__global__ void __launch_bounds__(256) wt_gather_transpose_kernel(
    const float* __restrict__ weight,
    const void* __restrict__ idx_raw,
    const int* __restrict__ t_ptr)
{
    __shared__ float tile[32][33];
    int bid = blockIdx.x;
    int c = bid >> 6;
    int rem = bid & 63;
    int kt = rem >> 3, nt = rem & 7;

    int t = t_ptr ? *t_ptr : 3;   // low 32-bit word valid for int32 and int64
    int ch = sel_index(idx_raw, c);

    const float* src = weight + (((size_t)ch * TILES + t) << 16);
    int tx = threadIdx.x & 31, ty = threadIdx.x >> 5;

#pragma unroll
    for (int i = 0; i < 4; ++i)
        tile[ty + i * 8][tx] = src[(size_t)(kt * 32 + ty + i * 8) * 256 + nt * 32 + tx];
    __syncthreads();

    __half* dst = g_wt + (((size_t)c * 256 + nt * 32) << 8) + kt * 32;
#pragma unroll
    for (int i = 0; i < 4; ++i)
        dst[(size_t)(ty + i * 8) * 256 + tx] = __float2half_rn(tile[tx][ty + i * 8]);
}

// ---------------------------------------------------------------------------
// Main kernel: one CTA per (channel, 64-pt tile), FULL 256 output columns,
// processed as two sequential 128-col phases sharing one fully-resident
// 32 KB fp16 A tile (4 chunk slots of 64x64 halves, written once).
// Combines R10 (minimal work: x read/converted exactly once, full-K A) with
// R12 (occupancy: 3 CTAs/SM = 24 warps in 3 independent barrier domains).
// 256 threads / 8 warps (2m x 4n), warp tile 32x32, mma.sync.m16n8k16.
// 3 CTAs/SM: regs ~80, smem 66 KB/CTA (198 KB/SM).
// ---------------------------------------------------------------------------
#define OFF_A    0u          // 4 slots x 8192 B (slot kc at kc*8192)
#define OFF_B0   32768u
#define OFF_B1   49152u
#define OFF_BIAS 65536u      // 256 floats
#define SMEM_DYN (66560u + 1024u)   // + pad for 1024B alignment

__global__ void __launch_bounds__(256, 3)
adaptive_linear_main_kernel(
    const float* __restrict__ x,
    const float* __restrict__ bias,
    const void* __restrict__ idx_raw,
    const int* __restrict__ t_ptr,
    float* __restrict__ out)
{
    extern __shared__ char dyn_smem[];
    uint32_t raw = smem_u32(dyn_smem);
    uint32_t sb = (raw + 1023u) & ~1023u;      // 1024B-aligned base for SW128
    char* sp = dyn_smem + (sb - raw);

    int tid = threadIdx.x;
    int wid = tid >> 5, lid = tid & 31;
    int c  = blockIdx.y;
    int m0 = blockIdx.x * 64;

    int t = t_ptr ? *t_ptr : 3;
    int ch = sel_index(idx_raw, c);
    ((float*)(sp + OFF_BIAS))[tid] = bias[(((size_t)ch * TILES + t) << 8) + tid];

    const float*  xA = x + (((size_t)c * PTS + m0) << 8);
    const __half* wBase = g_wt + ((size_t)c << 16);

    // per-thread load mapping
    int arow = tid >> 4;            // A: 64 rows, 16 threads/row, 4 row-groups
    int aq   = tid & 15;            // float4 index within 64-float chunk row
    int bn   = tid >> 1;            // B: 128 rows, 2 threads/row
    int bj0  = (tid & 1) * 4;       // 4 x 16B segments each

    float4 pa[4];                   // A staging registers (16 floats)

    // ---- A chunk LDG into regs (64 rows x 64 k, coalesced) ----------------
    auto ldgA = [&](int kc) {
        const float* base = xA + kc * 64 + aq * 4;
#pragma unroll
        for (int i = 0; i < 4; ++i)
            pa[i] = *(const float4*)(base + ((size_t)(arow + i * 16) << 8));
    };
    // ---- A regs -> fp16 swizzled STS into slot kc -------------------------
    auto stsA = [&](int kc) {
        uint32_t abase = OFF_A + (uint32_t)kc * 8192u;
#pragma unroll
        for (int i = 0; i < 4; ++i) {
            __half2 h0 = __floats2half2_rn(pa[i].x, pa[i].y);
            __half2 h1 = __floats2half2_rn(pa[i].z, pa[i].w);
            uint2 u;
            u.x = *reinterpret_cast<uint32_t*>(&h0);
            u.y = *reinterpret_cast<uint32_t*>(&h1);
            uint32_t o = (uint32_t)((arow + i * 16) * 128 + aq * 8);
            *reinterpret_cast<uint2*>(sp + abase + SWZ128(o)) = u;
        }
    };
    // ---- B chunk cp.async (phase p selects 128-col half of W) -------------
    auto cpB = [&](int p, int kc, uint32_t bbase) {
        const __half* wB = wBase + ((size_t)p << 15);
#pragma unroll
        for (int i = 0; i < 4; ++i) {
            int j = bj0 + i;
            uint32_t o = (uint32_t)(bn * 128 + j * 16);
            const __half* g = wB + ((size_t)bn << 8) + kc * 64 + j * 8;
            CP_ASYNC16(sb + bbase + SWZ128(o), g);
        }
    };

    // warp tile origin (8 warps: 2 m x 4 n)
    int mrow0 = (wid & 1) * 32;
    int ncol0 = (wid >> 1) * 32;
    // ldmatrix per-lane bases
    uint32_t aRow  = (uint32_t)(mrow0 + (lid & 15));
    uint32_t aKoff = (uint32_t)((lid >> 4) * 16);          // bytes
    uint32_t bRow  = (uint32_t)(ncol0 + ((lid >> 4) << 3) + (lid & 7));
    uint32_t bKoff = (uint32_t)(((lid >> 3) & 1) * 16);    // bytes

    float acc[2][4][4];
    auto zero_acc = [&]() {
#pragma unroll
        for (int mt = 0; mt < 2; ++mt)
#pragma unroll
            for (int nt = 0; nt < 4; ++nt)
#pragma unroll
                for (int r = 0; r < 4; ++r) acc[mt][nt][r] = 0.f;
    };

    // ---- one 16-wide k-step of chunk kc: 4 LDSM + 8 MMA, interleaved ------
    auto compute_ks = [&](int kc, uint32_t bb, int ks) {
        uint32_t ab = sb + OFF_A + (uint32_t)kc * 8192u;
        uint32_t a[2][4];
        uint32_t b[2][4];
#pragma unroll
        for (int mt = 0; mt < 2; ++mt) {
            uint32_t o = (aRow + mt * 16) * 128 + ks * 32 + aKoff;
            ldmx4(a[mt], ab + SWZ128(o));
        }
        {
            uint32_t o = (bRow + 0) * 128 + ks * 32 + bKoff;
            ldmx4(b[0], bb + SWZ128(o));
        }
#pragma unroll
        for (int mt = 0; mt < 2; ++mt)
#pragma unroll
            for (int nt = 0; nt < 2; ++nt)
                mma16816(acc[mt][nt], a[mt], &b[0][nt * 2]);
        {
            uint32_t o = (bRow + 16) * 128 + ks * 32 + bKoff;
            ldmx4(b[1], bb + SWZ128(o));
        }
#pragma unroll
        for (int mt = 0; mt < 2; ++mt)
#pragma unroll
            for (int nt = 2; nt < 4; ++nt)
                mma16816(acc[mt][nt], a[mt], &b[1][(nt - 2) * 2]);
    };

    // ---- epilogue: accums + bias -> GMEM for column base nb ---------------
    auto epilogue = [&](int nb) {
        const float* bsm = (const float*)(sp + OFF_BIAS);
        int r0 = lid >> 2;
        int c0 = 2 * (lid & 3);
#pragma unroll
        for (int mt = 0; mt < 2; ++mt) {
            size_t rowg = (size_t)c * PTS + m0 + mrow0 + mt * 16 + r0;
#pragma unroll
            for (int nt = 0; nt < 4; ++nt) {
                int col = nb + ncol0 + nt * 8 + c0;
                float b0 = bsm[col], b1 = bsm[col + 1];
                float2 v0 = make_float2(acc[mt][nt][0] + b0, acc[mt][nt][1] + b1);
                float2 v1 = make_float2(acc[mt][nt][2] + b0, acc[mt][nt][3] + b1);
                *reinterpret_cast<float2*>(out + (rowg << 8) + col) = v0;
                *reinterpret_cast<float2*>(out + ((rowg + 8) << 8) + col) = v1;
            }
        }
    };

    zero_acc();

    // ---- prologue: A chunk 0 + B(phase0, chunk0) --------------------------
    cpB(0, 0, OFF_B0);
    CP_COMMIT();
    ldgA(0);
    stsA(0);
    CP_WAIT0();
    __syncthreads();

    // ---- phase 1: compute n-cols [0,128) while filling A ------------------
    for (int kc = 0; kc < 4; ++kc) {
        uint32_t bb  = sb + ((kc & 1) ? OFF_B1 : OFF_B0);
        uint32_t bbN = (kc & 1) ? OFF_B0 : OFF_B1;

        if (kc < 3) {
            cpB(0, kc + 1, bbN);
            CP_COMMIT();
            ldgA(kc + 1);           // LDG issued two compute blocks before STS
        } else {
            // buf0 idle since end of kc==2 (sync passed): preload phase-2 ch0
            cpB(1, 0, OFF_B0);
            CP_COMMIT();
        }

        compute_ks(kc, bb, 0);
        compute_ks(kc, bb, 1);
        if (kc < 3) stsA(kc + 1);
        compute_ks(kc, bb, 2);
        compute_ks(kc, bb, 3);

        if (kc < 3) {
            CP_WAIT0();
            __syncthreads();
        }
    }

    // accs complete (registers) — overlap STG with the in-flight cp.async
    epilogue(0);
    zero_acc();
    CP_WAIT0();
    __syncthreads();

    // ---- phase 2: compute n-cols [128,256); A fully resident --------------
    for (int kc = 0; kc < 4; ++kc) {
        uint32_t bb  = sb + ((kc & 1) ? OFF_B1 : OFF_B0);
        uint32_t bbN = (kc & 1) ? OFF_B0 : OFF_B1;

        if (kc < 3) {
            cpB(1, kc + 1, bbN);
            CP_COMMIT();
        }

        compute_ks(kc, bb, 0);
        compute_ks(kc, bb, 1);
        compute_ks(kc, bb, 2);
        compute_ks(kc, bb, 3);

        if (kc < 3) {
            CP_WAIT0();
            __syncthreads();
        }
    }

    epilogue(128);
}

// ---------------------------------------------------------------------------
// kernel_launch: pre-pass (gather/transpose/convert weights) then main GEMM.
// Inputs (metadata order): x, weight, bias, indices, t
// ---------------------------------------------------------------------------
extern "C" void kernel_launch(void* const* d_in, const int* in_sizes, int n_in,
                              void* d_out, int out_size)
{
    const float* x       = (const float*)d_in[0];
    const float* weight  = (const float*)d_in[1];
    const float* bias    = (const float*)d_in[2];
    const void*  indices = d_in[3];
    const int*   t_ptr   = (n_in >= 5) ? (const int*)d_in[4] : nullptr;
    float* out = (float*)d_out;

    cudaFuncSetAttribute(adaptive_linear_main_kernel,
                         cudaFuncAttributeMaxDynamicSharedMemorySize, SMEM_DYN);

    wt_gather_transpose_kernel<<<N_SEL * 64, 256>>>(weight, indices, t_ptr);
    adaptive_linear_main_kernel<<<dim3(32, N_SEL), 256, SMEM_DYN>>>(
        x, bias, indices, t_ptr, out);
}